// round 5
// baseline (speedup 1.0000x reference)
#include <cuda_runtime.h>
#include <cuda_bf16.h>
#include <math.h>
#include <cstdint>

#define BB 8
#define SS 2048
#define DD 768
#define BSD (BB*SS*DD)

// Scratch: Q, K, Vt, x_rounded, W_rounded[3]
__device__ __align__(16) float g_scr[4ll*BSD + 3ll*DD*DD];

// ---------------- helpers ----------------
__device__ __forceinline__ uint32_t smem_u32(const void* p) {
    uint32_t a;
    asm("{ .reg .u64 t; cvta.to.shared.u64 t, %1; cvt.u32.u64 %0, t; }" : "=r"(a) : "l"(p));
    return a;
}
__device__ __forceinline__ float rna_tf32(float v) {
    uint32_t u; asm("cvt.rna.tf32.f32 %0, %1;" : "=r"(u) : "f"(v));
    return __uint_as_float(u);
}
#define CP_ASYNC16(dst, src) asm volatile("cp.async.cg.shared.global [%0], [%1], 16;" :: "r"(dst), "l"(src))
#define CP_COMMIT() asm volatile("cp.async.commit_group;" ::: "memory")
__device__ __forceinline__ void cp_wait(int n) {
    if (n <= 0)      asm volatile("cp.async.wait_group 0;" ::: "memory");
    else if (n == 1) asm volatile("cp.async.wait_group 1;" ::: "memory");
    else             asm volatile("cp.async.wait_group 2;" ::: "memory");
}

__device__ __forceinline__ void mma1688(float* d, const uint32_t* a, const uint32_t* b) {
    asm volatile(
        "mma.sync.aligned.m16n8k8.row.col.f32.tf32.tf32.f32 "
        "{%0,%1,%2,%3}, {%4,%5,%6,%7}, {%8,%9}, {%0,%1,%2,%3};"
        : "+f"(d[0]), "+f"(d[1]), "+f"(d[2]), "+f"(d[3])
        : "r"(a[0]), "r"(a[1]), "r"(a[2]), "r"(a[3]), "r"(b[0]), "r"(b[1]));
}

// ---------------- tiled tf32 GEMM-NT ----------------
// C[m,n] = alpha * sum_k A[m,k]*B[n,k]
// CTA tile 128x128, BK=32, 4 warps (2 M x 2 N), warp tile 64x64.
// 2 CTAs/SM so barrier/pipeline stalls in one CTA hide behind the other's MMAs.
// mode 0: plain; 1: tf32-rounded store; 2: transposed (Vt) rounded store
#define BLK_M 128
#define BLK_N 128
#define BK 32
#define NBUF 3
#define LDA_S 36
#define STAGE_FLOATS (BLK_M*LDA_S + BLK_N*LDA_S)
#define STAGE_BYTES (STAGE_FLOATS*4)
#define SMEM_TOTAL (NBUF*STAGE_BYTES)
#define EPI_LD 132   // multiple of 4 -> float4-aligned rows

__device__ __forceinline__ void load_stage(uint32_t sbase, const float* A, const float* B,
                                           int lda, int ldb, int k0, int tid) {
#pragma unroll
    for (int t = 0; t < 8; t++) {       // A: 128 rows x 8 chunks of 16B
        int idx = tid + t * 128;
        int row = idx >> 3, ck = idx & 7;
        CP_ASYNC16(sbase + (uint32_t)(row * LDA_S + ck * 4) * 4,
                   A + (size_t)row * lda + k0 + ck * 4);
    }
    uint32_t bb = sbase + BLK_M * LDA_S * 4;
#pragma unroll
    for (int t = 0; t < 8; t++) {       // B: 128 rows x 8 chunks
        int idx = tid + t * 128;
        int row = idx >> 3, ck = idx & 7;
        CP_ASYNC16(bb + (uint32_t)(row * LDA_S + ck * 4) * 4,
                   B + (size_t)row * ldb + k0 + ck * 4);
    }
}

__global__ void __launch_bounds__(128, 2) gemm_tc(
    const float* __restrict__ A, const float* __restrict__ B, float* __restrict__ C,
    int Ktot, long long strA, long long strB, long long strC,
    int lda, int ldb, int ldc, float alpha, int mode)
{
    extern __shared__ char smem[];
    const uint32_t sb = smem_u32(smem);
    const int tid = threadIdx.x, wid = tid >> 5, lid = tid & 31;
    const int wm = wid & 1, wn = wid >> 1;
    const int m0 = blockIdx.x * BLK_M, n0 = blockIdx.y * BLK_N;

    A += blockIdx.z * strA + (size_t)m0 * lda;
    B += blockIdx.z * strB + (size_t)n0 * ldb;
    C += blockIdx.z * strC;

    float acc[4][8][4];
#pragma unroll
    for (int i = 0; i < 4; i++)
#pragma unroll
        for (int j = 0; j < 8; j++)
#pragma unroll
            for (int k = 0; k < 4; k++) acc[i][j][k] = 0.f;

    const int iters = Ktot / BK;
    load_stage(sb + 0 * STAGE_BYTES, A, B, lda, ldb, 0, tid);  CP_COMMIT();
    load_stage(sb + 1 * STAGE_BYTES, A, B, lda, ldb, BK, tid); CP_COMMIT();

    for (int i = 0; i < iters; i++) {
        if (i + 2 < iters) {
            load_stage(sb + ((i + 2) % NBUF) * STAGE_BYTES, A, B, lda, ldb, (i + 2) * BK, tid);
            CP_COMMIT();
        }
        int nw = iters - 1 - i; if (nw > 2) nw = 2;
        cp_wait(nw);
        __syncthreads();

        const float* As = (const float*)(smem + (i % NBUF) * STAGE_BYTES);
        const float* Bs = As + BLK_M * LDA_S;
        const int rl = lid >> 2, cl = lid & 3;

#pragma unroll
        for (int ks = 0; ks < BK / 8; ks++) {
            uint32_t af[4][4], bf[8][2];
            const int kk = ks * 8 + cl;
#pragma unroll
            for (int mt = 0; mt < 4; mt++) {
                int ra = wm * 64 + mt * 16 + rl;
                af[mt][0] = __float_as_uint(As[ra * LDA_S + kk]);
                af[mt][1] = __float_as_uint(As[(ra + 8) * LDA_S + kk]);
                af[mt][2] = __float_as_uint(As[ra * LDA_S + kk + 4]);
                af[mt][3] = __float_as_uint(As[(ra + 8) * LDA_S + kk + 4]);
            }
#pragma unroll
            for (int nt = 0; nt < 8; nt++) {
                int rb = wn * 64 + nt * 8 + rl;
                bf[nt][0] = __float_as_uint(Bs[rb * LDA_S + kk]);
                bf[nt][1] = __float_as_uint(Bs[rb * LDA_S + kk + 4]);
            }
#pragma unroll
            for (int mt = 0; mt < 4; mt++)
#pragma unroll
                for (int nt = 0; nt < 8; nt++)
                    mma1688(acc[mt][nt], af[mt], bf[nt]);
        }
        __syncthreads();
    }

    // ---- epilogue: regs -> smem (alpha/round) -> gmem ----
    float* epis = (float*)smem;
    const int rl = lid >> 2, cl = lid & 3;
#pragma unroll
    for (int mt = 0; mt < 4; mt++) {
#pragma unroll
        for (int nt = 0; nt < 8; nt++) {
            int r = wm * 64 + mt * 16 + rl;
            int c = wn * 64 + nt * 8 + 2 * cl;
            float v0 = alpha * acc[mt][nt][0], v1 = alpha * acc[mt][nt][1];
            float v2 = alpha * acc[mt][nt][2], v3 = alpha * acc[mt][nt][3];
            if (mode != 0) { v0 = rna_tf32(v0); v1 = rna_tf32(v1); v2 = rna_tf32(v2); v3 = rna_tf32(v3); }
            epis[r * EPI_LD + c] = v0;
            epis[r * EPI_LD + c + 1] = v1;
            epis[(r + 8) * EPI_LD + c] = v2;
            epis[(r + 8) * EPI_LD + c + 1] = v3;
        }
    }
    __syncthreads();

    if (mode != 2) {
#pragma unroll
        for (int it = 0; it < 32; it++) {
            int idx = tid + it * 128;
            int r = idx >> 5, c4 = (idx & 31) * 4;
            float4 v = *(const float4*)(epis + r * EPI_LD + c4);
            *(float4*)(C + (size_t)(m0 + r) * ldc + n0 + c4) = v;
        }
    } else {
        // C is Vt[B][D][S]
        const int bb = m0 >> 11, s0 = m0 & 2047;
        float* T = C + (size_t)bb * DD * SS + s0;
#pragma unroll
        for (int it = 0; it < 128; it++) {
            int idx = tid + it * 128;
            int c = idx >> 7, r = idx & 127;
            T[(size_t)(n0 + c) * SS + r] = epis[r * EPI_LD + c];
        }
    }
}

// ---------------- tf32 rounding pre-pass ----------------
__global__ __launch_bounds__(256) void round_tf32_kernel(const float* __restrict__ in,
                                                         float* __restrict__ out, int n4) {
    int i = blockIdx.x * 256 + threadIdx.x;
    if (i < n4) {
        float4 v = ((const float4*)in)[i];
        v.x = rna_tf32(v.x); v.y = rna_tf32(v.y); v.z = rna_tf32(v.z); v.w = rna_tf32(v.w);
        ((float4*)out)[i] = v;
    }
}

// ---------------- softmax (in place, tf32-rounded output, float4) ----------------
__global__ __launch_bounds__(256) void softmax_kernel(float* __restrict__ attn) {
    float4* p = (float4*)(attn + (size_t)blockIdx.x * SS);
    const int t = threadIdx.x;
    const int lid = t & 31, wrp = t >> 5;
    __shared__ float red[8];

    float4 v0 = p[t], v1 = p[t + 256];
    float m = fmaxf(fmaxf(fmaxf(v0.x, v0.y), fmaxf(v0.z, v0.w)),
                    fmaxf(fmaxf(v1.x, v1.y), fmaxf(v1.z, v1.w)));
#pragma unroll
    for (int s = 16; s > 0; s >>= 1) m = fmaxf(m, __shfl_xor_sync(0xffffffffu, m, s));
    if (lid == 0) red[wrp] = m;
    __syncthreads();
    m = fmaxf(fmaxf(fmaxf(red[0], red[1]), fmaxf(red[2], red[3])),
              fmaxf(fmaxf(red[4], red[5]), fmaxf(red[6], red[7])));
    __syncthreads();

    v0.x = __expf(v0.x - m); v0.y = __expf(v0.y - m); v0.z = __expf(v0.z - m); v0.w = __expf(v0.w - m);
    v1.x = __expf(v1.x - m); v1.y = __expf(v1.y - m); v1.z = __expf(v1.z - m); v1.w = __expf(v1.w - m);
    float sum = (v0.x + v0.y) + (v0.z + v0.w) + (v1.x + v1.y) + (v1.z + v1.w);
#pragma unroll
    for (int s = 16; s > 0; s >>= 1) sum += __shfl_xor_sync(0xffffffffu, sum, s);
    if (lid == 0) red[wrp] = sum;
    __syncthreads();
    sum = (red[0] + red[1]) + (red[2] + red[3]) + (red[4] + red[5]) + (red[6] + red[7]);
    float inv = 1.f / sum;

    v0.x = rna_tf32(v0.x * inv); v0.y = rna_tf32(v0.y * inv);
    v0.z = rna_tf32(v0.z * inv); v0.w = rna_tf32(v0.w * inv);
    v1.x = rna_tf32(v1.x * inv); v1.y = rna_tf32(v1.y * inv);
    v1.z = rna_tf32(v1.z * inv); v1.w = rna_tf32(v1.w * inv);
    p[t] = v0; p[t + 256] = v1;
}

// ---------------- launcher ----------------
extern "C" void kernel_launch(void* const* d_in, const int* in_sizes, int n_in,
                              void* d_out, int out_size)
{
    const float* x  = (const float*)d_in[0];
    const float* Wq = (const float*)d_in[1];
    const float* Wk = (const float*)d_in[2];
    const float* Wv = (const float*)d_in[3];

    float* out_wv   = (float*)d_out;
    float* out_attn = (float*)d_out + BSD;

    float* base = nullptr;
    cudaGetSymbolAddress((void**)&base, g_scr);
    float* Q   = base;
    float* Km  = base + (long long)BSD;
    float* Vt  = base + 2ll * BSD;
    float* xr  = base + 3ll * BSD;
    float* Wr  = base + 4ll * BSD;

    static int smem_set = 0;
    if (!smem_set) {
        cudaFuncSetAttribute(gemm_tc, cudaFuncAttributeMaxDynamicSharedMemorySize, SMEM_TOTAL);
        smem_set = 1;
    }

    // 0) round inputs to tf32 so MMA products are exact
    round_tf32_kernel<<<(BSD / 4 + 255) / 256, 256>>>(x, xr, BSD / 4);
    round_tf32_kernel<<<(DD * DD / 4 + 255) / 256, 256>>>(Wq, Wr,               DD * DD / 4);
    round_tf32_kernel<<<(DD * DD / 4 + 255) / 256, 256>>>(Wk, Wr + DD * DD,     DD * DD / 4);
    round_tf32_kernel<<<(DD * DD / 4 + 255) / 256, 256>>>(Wv, Wr + 2 * DD * DD, DD * DD / 4);

    // 1) QKV projections (NT): Q/K rounded, V -> transposed rounded Vt
    {
        dim3 grid(BB * SS / BLK_M, DD / BLK_N, 1);
        gemm_tc<<<grid, 128, SMEM_TOTAL>>>(xr, Wr,               Q,  DD, 0, 0, 0, DD, DD, DD, 1.0f, 1);
        gemm_tc<<<grid, 128, SMEM_TOTAL>>>(xr, Wr + DD * DD,     Km, DD, 0, 0, 0, DD, DD, DD, 1.0f, 1);
        gemm_tc<<<grid, 128, SMEM_TOTAL>>>(xr, Wr + 2 * DD * DD, Vt, DD, 0, 0, 0, DD, DD, DD, 1.0f, 2);
    }

    // 2) scores = Q K^T / sqrt(D) -> attn (unnormalized)
    {
        dim3 grid(SS / BLK_M, SS / BLK_N, BB);
        gemm_tc<<<grid, 128, SMEM_TOTAL>>>(Q, Km, out_attn, DD,
                                           (long long)SS * DD, (long long)SS * DD, (long long)SS * SS,
                                           DD, DD, SS, 1.0f / sqrtf((float)DD), 0);
    }

    // 3) softmax (tf32-rounded weights)
    softmax_kernel<<<BB * SS, 256>>>(out_attn);

    // 4) weighted = attn @ V (NT against Vt)
    {
        dim3 grid(SS / BLK_M, DD / BLK_N, BB);
        gemm_tc<<<grid, 128, SMEM_TOTAL>>>(out_attn, Vt, out_wv, SS,
                                           (long long)SS * SS, (long long)DD * SS, (long long)SS * DD,
                                           SS, SS, DD, 1.0f, 0);
    }
}

// round 6
// speedup vs baseline: 1.1110x; 1.1110x over previous
#include <cuda_runtime.h>
#include <cuda_bf16.h>
#include <math.h>
#include <cstdint>

#define BB 8
#define SS 2048
#define DD 768
#define BSD (BB*SS*DD)

// Scratch: Q, K, Vt, x_rounded, W_rounded[3]
__device__ __align__(16) float g_scr[4ll*BSD + 3ll*DD*DD];

// ---------------- helpers ----------------
__device__ __forceinline__ uint32_t smem_u32(const void* p) {
    uint32_t a;
    asm("{ .reg .u64 t; cvta.to.shared.u64 t, %1; cvt.u32.u64 %0, t; }" : "=r"(a) : "l"(p));
    return a;
}
__device__ __forceinline__ float rna_tf32(float v) {
    uint32_t u; asm("cvt.rna.tf32.f32 %0, %1;" : "=r"(u) : "f"(v));
    return __uint_as_float(u);
}
#define CP_ASYNC16(dst, src) asm volatile("cp.async.cg.shared.global [%0], [%1], 16;" :: "r"(dst), "l"(src))
#define CP_COMMIT() asm volatile("cp.async.commit_group;" ::: "memory")
__device__ __forceinline__ void cp_wait(int n) {
    if (n <= 0)      asm volatile("cp.async.wait_group 0;" ::: "memory");
    else if (n == 1) asm volatile("cp.async.wait_group 1;" ::: "memory");
    else             asm volatile("cp.async.wait_group 2;" ::: "memory");
}

__device__ __forceinline__ void mma1688(float* d, const uint32_t* a, const uint32_t* b) {
    asm volatile(
        "mma.sync.aligned.m16n8k8.row.col.f32.tf32.tf32.f32 "
        "{%0,%1,%2,%3}, {%4,%5,%6,%7}, {%8,%9}, {%0,%1,%2,%3};"
        : "+f"(d[0]), "+f"(d[1]), "+f"(d[2]), "+f"(d[3])
        : "r"(a[0]), "r"(a[1]), "r"(a[2]), "r"(a[3]), "r"(b[0]), "r"(b[1]));
}

// ---------------- tiled tf32 GEMM core (round-4 config) ----------------
// CTA tile 256x128, BK=32, 8 warps (4 M x 2 N), warp tile 64x64, NBUF=4.
#define BLK_M 256
#define BLK_N 128
#define BK 32
#define NBUF 4
#define LDA_S 36
#define STAGE_FLOATS (BLK_M*LDA_S + BLK_N*LDA_S)
#define STAGE_BYTES (STAGE_FLOATS*4)
#define SMEM_TOTAL (NBUF*STAGE_BYTES)
#define EPI_LD 132   // multiple of 4 -> float4-aligned rows

__device__ __forceinline__ void load_stage(uint32_t sbase, const float* A, const float* B,
                                           int lda, int ldb, int k0, int tid) {
#pragma unroll
    for (int t = 0; t < 8; t++) {       // A: 256 rows x 8 chunks
        int idx = tid + t * 256;
        int row = idx >> 3, ck = idx & 7;
        CP_ASYNC16(sbase + (uint32_t)(row * LDA_S + ck * 4) * 4,
                   A + (size_t)row * lda + k0 + ck * 4);
    }
    uint32_t bb = sbase + BLK_M * LDA_S * 4;
#pragma unroll
    for (int t = 0; t < 4; t++) {       // B: 128 rows x 8 chunks
        int idx = tid + t * 256;
        int row = idx >> 3, ck = idx & 7;
        CP_ASYNC16(bb + (uint32_t)(row * LDA_S + ck * 4) * 4,
                   B + (size_t)row * ldb + k0 + ck * 4);
    }
}

// core mainloop: accumulates into acc
__device__ __forceinline__ void gemm_mainloop(
    const char* smem, uint32_t sb, const float* A, const float* B,
    int Ktot, int lda, int ldb, int tid, int wm, int wn, int lid,
    float acc[4][8][4])
{
    const int iters = Ktot / BK;
    load_stage(sb + 0 * STAGE_BYTES, A, B, lda, ldb, 0, tid);  CP_COMMIT();
    load_stage(sb + 1 * STAGE_BYTES, A, B, lda, ldb, BK, tid); CP_COMMIT();

    for (int i = 0; i < iters; i++) {
        if (i + 2 < iters) {
            load_stage(sb + ((i + 2) % NBUF) * STAGE_BYTES, A, B, lda, ldb, (i + 2) * BK, tid);
            CP_COMMIT();
        }
        int nw = iters - 1 - i; if (nw > 2) nw = 2;
        cp_wait(nw);
        __syncthreads();

        const float* As = (const float*)(smem + (i % NBUF) * STAGE_BYTES);
        const float* Bs = As + BLK_M * LDA_S;
        const int rl = lid >> 2, cl = lid & 3;

#pragma unroll
        for (int ks = 0; ks < BK / 8; ks++) {
            uint32_t af[4][4], bf[8][2];
            const int kk = ks * 8 + cl;
#pragma unroll
            for (int mt = 0; mt < 4; mt++) {
                int ra = wm * 64 + mt * 16 + rl;
                af[mt][0] = __float_as_uint(As[ra * LDA_S + kk]);
                af[mt][1] = __float_as_uint(As[(ra + 8) * LDA_S + kk]);
                af[mt][2] = __float_as_uint(As[ra * LDA_S + kk + 4]);
                af[mt][3] = __float_as_uint(As[(ra + 8) * LDA_S + kk + 4]);
            }
#pragma unroll
            for (int nt = 0; nt < 8; nt++) {
                int rb = wn * 64 + nt * 8 + rl;
                bf[nt][0] = __float_as_uint(Bs[rb * LDA_S + kk]);
                bf[nt][1] = __float_as_uint(Bs[rb * LDA_S + kk + 4]);
            }
#pragma unroll
            for (int mt = 0; mt < 4; mt++)
#pragma unroll
                for (int nt = 0; nt < 8; nt++)
                    mma1688(acc[mt][nt], af[mt], bf[nt]);
        }
    }
    __syncthreads();
}

__device__ __forceinline__ void epilogue_store(
    char* smem, float* C, int ldc, int m0, int n0,
    int tid, int wm, int wn, int lid, float alpha, int mode,
    float acc[4][8][4])
{
    float* epis = (float*)smem;
    const int rl = lid >> 2, cl = lid & 3;
#pragma unroll
    for (int mt = 0; mt < 4; mt++) {
#pragma unroll
        for (int nt = 0; nt < 8; nt++) {
            int r = wm * 64 + mt * 16 + rl;
            int c = wn * 64 + nt * 8 + 2 * cl;
            float v0 = alpha * acc[mt][nt][0], v1 = alpha * acc[mt][nt][1];
            float v2 = alpha * acc[mt][nt][2], v3 = alpha * acc[mt][nt][3];
            if (mode != 0) { v0 = rna_tf32(v0); v1 = rna_tf32(v1); v2 = rna_tf32(v2); v3 = rna_tf32(v3); }
            epis[r * EPI_LD + c] = v0;
            epis[r * EPI_LD + c + 1] = v1;
            epis[(r + 8) * EPI_LD + c] = v2;
            epis[(r + 8) * EPI_LD + c + 1] = v3;
        }
    }
    __syncthreads();

    if (mode != 2) {
#pragma unroll
        for (int it = 0; it < 32; it++) {
            int idx = tid + it * 256;
            int r = idx >> 5, c4 = (idx & 31) * 4;
            float4 v = *(const float4*)(epis + r * EPI_LD + c4);
            *(float4*)(C + (size_t)(m0 + r) * ldc + n0 + c4) = v;
        }
    } else {
        // C is Vt[B][D][S]
        const int bb = m0 >> 11, s0 = m0 & 2047;
        float* T = C + (size_t)bb * DD * SS + s0;
#pragma unroll
        for (int it = 0; it < 128; it++) {
            int idx = tid + it * 256;
            int r = idx & 255, c = idx >> 8;
            T[(size_t)(n0 + c) * SS + r] = epis[r * EPI_LD + c];
        }
    }
}

// ---------------- generic GEMM-NT (scores, AV) ----------------
__global__ void __launch_bounds__(256, 1) gemm_tc(
    const float* __restrict__ A, const float* __restrict__ B, float* __restrict__ C,
    int Ktot, long long strA, long long strB, long long strC,
    int lda, int ldb, int ldc, float alpha, int mode)
{
    extern __shared__ char smem[];
    const uint32_t sb = smem_u32(smem);
    const int tid = threadIdx.x, wid = tid >> 5, lid = tid & 31;
    const int wm = wid & 3, wn = wid >> 2;
    const int m0 = blockIdx.x * BLK_M, n0 = blockIdx.y * BLK_N;

    A += blockIdx.z * strA + (size_t)m0 * lda;
    B += blockIdx.z * strB + (size_t)n0 * ldb;
    C += blockIdx.z * strC;

    float acc[4][8][4];
#pragma unroll
    for (int i = 0; i < 4; i++)
#pragma unroll
        for (int j = 0; j < 8; j++)
#pragma unroll
            for (int k = 0; k < 4; k++) acc[i][j][k] = 0.f;

    gemm_mainloop(smem, sb, A, B, Ktot, lda, ldb, tid, wm, wn, lid, acc);
    epilogue_store(smem, C, ldc, m0, n0, tid, wm, wn, lid, alpha, mode, acc);
}

// ---------------- fused QKV projection (z selects weight/output) ----------------
__global__ void __launch_bounds__(256, 1) gemm_qkv(
    const float* __restrict__ xr, const float* __restrict__ Wr,
    float* __restrict__ Q, float* __restrict__ Km, float* __restrict__ Vt)
{
    extern __shared__ char smem[];
    const uint32_t sb = smem_u32(smem);
    const int tid = threadIdx.x, wid = tid >> 5, lid = tid & 31;
    const int wm = wid & 3, wn = wid >> 2;
    const int m0 = blockIdx.x * BLK_M, n0 = blockIdx.y * BLK_N;
    const int z = blockIdx.z;

    const float* A = xr + (size_t)m0 * DD;
    const float* B = Wr + (size_t)z * DD * DD + (size_t)n0 * DD;
    float* C = (z == 0) ? Q : (z == 1) ? Km : Vt;
    const int mode = (z == 2) ? 2 : 1;

    float acc[4][8][4];
#pragma unroll
    for (int i = 0; i < 4; i++)
#pragma unroll
        for (int j = 0; j < 8; j++)
#pragma unroll
            for (int k = 0; k < 4; k++) acc[i][j][k] = 0.f;

    gemm_mainloop(smem, sb, A, B, DD, DD, DD, tid, wm, wn, lid, acc);
    epilogue_store(smem, C, DD, m0, n0, tid, wm, wn, lid, 1.0f, mode, acc);
}

// ---------------- tf32 rounding pre-pass ----------------
__global__ __launch_bounds__(256) void round_tf32_kernel(const float* __restrict__ in,
                                                         float* __restrict__ out, int n4) {
    int i = blockIdx.x * 256 + threadIdx.x;
    if (i < n4) {
        float4 v = ((const float4*)in)[i];
        v.x = rna_tf32(v.x); v.y = rna_tf32(v.y); v.z = rna_tf32(v.z); v.w = rna_tf32(v.w);
        ((float4*)out)[i] = v;
    }
}

// ---------------- softmax (in place, tf32-rounded output, float4) ----------------
__global__ __launch_bounds__(256) void softmax_kernel(float* __restrict__ attn) {
    float4* p = (float4*)(attn + (size_t)blockIdx.x * SS);
    const int t = threadIdx.x;
    const int lid = t & 31, wrp = t >> 5;
    __shared__ float red[8];

    float4 v0 = p[t], v1 = p[t + 256];
    float m = fmaxf(fmaxf(fmaxf(v0.x, v0.y), fmaxf(v0.z, v0.w)),
                    fmaxf(fmaxf(v1.x, v1.y), fmaxf(v1.z, v1.w)));
#pragma unroll
    for (int s = 16; s > 0; s >>= 1) m = fmaxf(m, __shfl_xor_sync(0xffffffffu, m, s));
    if (lid == 0) red[wrp] = m;
    __syncthreads();
    m = fmaxf(fmaxf(fmaxf(red[0], red[1]), fmaxf(red[2], red[3])),
              fmaxf(fmaxf(red[4], red[5]), fmaxf(red[6], red[7])));
    __syncthreads();

    v0.x = __expf(v0.x - m); v0.y = __expf(v0.y - m); v0.z = __expf(v0.z - m); v0.w = __expf(v0.w - m);
    v1.x = __expf(v1.x - m); v1.y = __expf(v1.y - m); v1.z = __expf(v1.z - m); v1.w = __expf(v1.w - m);
    float sum = (v0.x + v0.y) + (v0.z + v0.w) + (v1.x + v1.y) + (v1.z + v1.w);
#pragma unroll
    for (int s = 16; s > 0; s >>= 1) sum += __shfl_xor_sync(0xffffffffu, sum, s);
    if (lid == 0) red[wrp] = sum;
    __syncthreads();
    sum = (red[0] + red[1]) + (red[2] + red[3]) + (red[4] + red[5]) + (red[6] + red[7]);
    float inv = 1.f / sum;

    v0.x = rna_tf32(v0.x * inv); v0.y = rna_tf32(v0.y * inv);
    v0.z = rna_tf32(v0.z * inv); v0.w = rna_tf32(v0.w * inv);
    v1.x = rna_tf32(v1.x * inv); v1.y = rna_tf32(v1.y * inv);
    v1.z = rna_tf32(v1.z * inv); v1.w = rna_tf32(v1.w * inv);
    p[t] = v0; p[t + 256] = v1;
}

// ---------------- launcher ----------------
extern "C" void kernel_launch(void* const* d_in, const int* in_sizes, int n_in,
                              void* d_out, int out_size)
{
    const float* x  = (const float*)d_in[0];
    const float* Wq = (const float*)d_in[1];
    const float* Wk = (const float*)d_in[2];
    const float* Wv = (const float*)d_in[3];

    float* out_wv   = (float*)d_out;
    float* out_attn = (float*)d_out + BSD;

    float* base = nullptr;
    cudaGetSymbolAddress((void**)&base, g_scr);
    float* Q   = base;
    float* Km  = base + (long long)BSD;
    float* Vt  = base + 2ll * BSD;
    float* xr  = base + 3ll * BSD;
    float* Wr  = base + 4ll * BSD;

    static int smem_set = 0;
    if (!smem_set) {
        cudaFuncSetAttribute(gemm_tc,  cudaFuncAttributeMaxDynamicSharedMemorySize, SMEM_TOTAL);
        cudaFuncSetAttribute(gemm_qkv, cudaFuncAttributeMaxDynamicSharedMemorySize, SMEM_TOTAL);
        smem_set = 1;
    }

    // 0) round inputs to tf32 so MMA products are exact
    round_tf32_kernel<<<(BSD / 4 + 255) / 256, 256>>>(x, xr, BSD / 4);
    round_tf32_kernel<<<(DD * DD / 4 + 255) / 256, 256>>>(Wq, Wr,               DD * DD / 4);
    round_tf32_kernel<<<(DD * DD / 4 + 255) / 256, 256>>>(Wk, Wr + DD * DD,     DD * DD / 4);
    round_tf32_kernel<<<(DD * DD / 4 + 255) / 256, 256>>>(Wv, Wr + 2 * DD * DD, DD * DD / 4);

    // 1) fused QKV projections: one launch, z = {Q, K, Vt}
    {
        dim3 grid(BB * SS / BLK_M, DD / BLK_N, 3);
        gemm_qkv<<<grid, 256, SMEM_TOTAL>>>(xr, Wr, Q, Km, Vt);
    }

    // 2) scores = Q K^T / sqrt(D) -> attn (unnormalized)
    {
        dim3 grid(SS / BLK_M, SS / BLK_N, BB);
        gemm_tc<<<grid, 256, SMEM_TOTAL>>>(Q, Km, out_attn, DD,
                                           (long long)SS * DD, (long long)SS * DD, (long long)SS * SS,
                                           DD, DD, SS, 1.0f / sqrtf((float)DD), 0);
    }

    // 3) softmax (tf32-rounded weights)
    softmax_kernel<<<BB * SS, 256>>>(out_attn);

    // 4) weighted = attn @ V (NT against Vt)
    {
        dim3 grid(SS / BLK_M, DD / BLK_N, BB);
        gemm_tc<<<grid, 256, SMEM_TOTAL>>>(out_attn, Vt, out_wv, SS,
                                           (long long)SS * SS, (long long)DD * SS, (long long)SS * DD,
                                           SS, SS, DD, 1.0f, 0);
    }
}